// round 2
// baseline (speedup 1.0000x reference)
#include <cuda_runtime.h>
#include <cuda_bf16.h>
#include <cstdint>

#define EPSF 1e-8f
#define NKEY 100000
#define NBLK 1563   // ceil(100000/64)

// ---------------- scratch (device globals; no allocs allowed) ----------------
__device__ __align__(16) __nv_bfloat16 g_simb[256 * NKEY];   // approx sims, bf16
__device__ __align__(16) float          g_qrelu[256 * 512];
__device__ __align__(16) __nv_bfloat16  g_qb[256 * 512];
__device__ __align__(16) float          g_qn[256];
__device__ __align__(16) int            g_topk[256 * 32];
__device__ __align__(16) float          g_hq[256 * 256];
__device__ __align__(16) float          g_M[8192 * 256];

// ---------------- K1: relu(q), bf16 copy, row norms ----------------
__global__ void k1_prep(const float* __restrict__ qf) {
    const int b = blockIdx.x, t = threadIdx.x;
    __shared__ float red[8];
    float s = 0.f;
#pragma unroll
    for (int i = 0; i < 2; i++) {
        int d = t + i * 256;
        float v = fmaxf(qf[b * 512 + d], 0.f);
        g_qrelu[b * 512 + d] = v;
        g_qb[b * 512 + d] = __float2bfloat16(v);
        s += v * v;
    }
    for (int o = 16; o; o >>= 1) s += __shfl_xor_sync(0xffffffffu, s, o);
    if ((t & 31) == 0) red[t >> 5] = s;
    __syncthreads();
    if (t == 0) {
        float tot = 0.f;
        for (int i = 0; i < 8; i++) tot += red[i];
        g_qn[b] = sqrtf(tot);
    }
}

// ---------------- K2: approx sim GEMM (bf16 mma.sync), kn fused ----------------
// block 256 thr (8 warps, 4Mx2N). Tile M=256 x N=64 keys, K chunks of 64.
__global__ void __launch_bounds__(256) k2_sim(const float* __restrict__ keys) {
    __shared__ __nv_bfloat16 As[256 * 72];
    __shared__ __nv_bfloat16 Bs[64 * 72];
    __shared__ float qn_s[256];
    __shared__ float kn_s[64];
    const int t = threadIdx.x;
    const int n0 = blockIdx.x * 64;
    qn_s[t] = g_qn[t];

    float acc[4][4][4];
#pragma unroll
    for (int a = 0; a < 4; a++)
#pragma unroll
        for (int b = 0; b < 4; b++)
#pragma unroll
            for (int c = 0; c < 4; c++) acc[a][b][c] = 0.f;

    float ssq = 0.f;
    const int lane = t & 31, warp = t >> 5;
    const int wm = warp >> 1, wn = warp & 1;
    const int brow = t >> 2;                // key row in tile, 0..63
    const int gn_row = n0 + brow;
    const bool rowok = gn_row < NKEY;
    const float* kptr = keys + (size_t)gn_row * 512 + (t & 3) * 16;

    for (int kt = 0; kt < 8; kt++) {
        const int k0 = kt * 64;
#pragma unroll
        for (int i = 0; i < 8; i++) {        // A: 256x64 bf16 from L2
            int c = t + i * 256;
            int m = c >> 3, kc = c & 7;
            const uint4 v = *reinterpret_cast<const uint4*>(&g_qb[m * 512 + k0 + kc * 8]);
            *reinterpret_cast<uint4*>(&As[m * 72 + kc * 8]) = v;
        }
        __nv_bfloat162 bv[8];                // B: keys fp32 -> bf16, sumsq fused
        if (rowok) {
#pragma unroll
            for (int j = 0; j < 4; j++) {
                float4 f = *reinterpret_cast<const float4*>(kptr + k0 + j * 4);
                ssq += f.x * f.x + f.y * f.y + f.z * f.z + f.w * f.w;
                bv[2 * j]     = __floats2bfloat162_rn(f.x, f.y);
                bv[2 * j + 1] = __floats2bfloat162_rn(f.z, f.w);
            }
        } else {
#pragma unroll
            for (int j = 0; j < 8; j++) bv[j] = __floats2bfloat162_rn(0.f, 0.f);
        }
        {
            __nv_bfloat162* bs2 = reinterpret_cast<__nv_bfloat162*>(&Bs[brow * 72 + (t & 3) * 16]);
#pragma unroll
            for (int j = 0; j < 8; j++) bs2[j] = bv[j];
        }
        __syncthreads();

#pragma unroll
        for (int kk16 = 0; kk16 < 4; kk16++) {
            const int kk = kk16 * 16;
            uint32_t af[4][4];
#pragma unroll
            for (int mi = 0; mi < 4; mi++) {
                int row = wm * 64 + mi * 16 + (lane & 15);
                int col = kk + ((lane >> 4) << 3);
                uint32_t addr = (uint32_t)__cvta_generic_to_shared(&As[row * 72 + col]);
                asm volatile("ldmatrix.sync.aligned.m8n8.x4.shared.b16 {%0,%1,%2,%3}, [%4];"
                             : "=r"(af[mi][0]), "=r"(af[mi][1]), "=r"(af[mi][2]), "=r"(af[mi][3])
                             : "r"(addr));
            }
            uint32_t bfr[4][2];
#pragma unroll
            for (int p = 0; p < 2; p++) {
                int g = lane >> 3, r = lane & 7;
                int nrow = wn * 32 + p * 16 + ((g >> 1) << 3) + r;
                int kcol = kk + ((g & 1) << 3);
                uint32_t addr = (uint32_t)__cvta_generic_to_shared(&Bs[nrow * 72 + kcol]);
                uint32_t r0, r1, r2, r3;
                asm volatile("ldmatrix.sync.aligned.m8n8.x4.shared.b16 {%0,%1,%2,%3}, [%4];"
                             : "=r"(r0), "=r"(r1), "=r"(r2), "=r"(r3) : "r"(addr));
                bfr[p * 2][0] = r0;     bfr[p * 2][1] = r1;
                bfr[p * 2 + 1][0] = r2; bfr[p * 2 + 1][1] = r3;
            }
#pragma unroll
            for (int mi = 0; mi < 4; mi++)
#pragma unroll
                for (int ni = 0; ni < 4; ni++)
                    asm volatile(
                        "mma.sync.aligned.m16n8k16.row.col.f32.bf16.bf16.f32 "
                        "{%0,%1,%2,%3}, {%4,%5,%6,%7}, {%8,%9}, {%0,%1,%2,%3};"
                        : "+f"(acc[mi][ni][0]), "+f"(acc[mi][ni][1]),
                          "+f"(acc[mi][ni][2]), "+f"(acc[mi][ni][3])
                        : "r"(af[mi][0]), "r"(af[mi][1]), "r"(af[mi][2]), "r"(af[mi][3]),
                          "r"(bfr[ni][0]), "r"(bfr[ni][1]));
        }
        __syncthreads();
    }

    // kn reduce across the 4 threads of each key row
    ssq += __shfl_xor_sync(0xffffffffu, ssq, 1);
    ssq += __shfl_xor_sync(0xffffffffu, ssq, 2);
    if ((t & 3) == 0) kn_s[brow] = sqrtf(ssq);
    __syncthreads();

    // epilogue: cosine scaling, store bf16 sims
#pragma unroll
    for (int mi = 0; mi < 4; mi++) {
        int m = wm * 64 + mi * 16 + (lane >> 2);
        float qn0 = qn_s[m], qn1 = qn_s[m + 8];
#pragma unroll
        for (int ni = 0; ni < 4; ni++) {
            int nl = wn * 32 + ni * 8 + ((lane & 3) << 1);
            int gn = n0 + nl;
            if (gn < NKEY) {
                float kn0 = kn_s[nl], kn1 = kn_s[nl + 1];
                float i0 = 1.f / fmaxf(qn0 * kn0, EPSF);
                float i1 = 1.f / fmaxf(qn0 * kn1, EPSF);
                float j0 = 1.f / fmaxf(qn1 * kn0, EPSF);
                float j1 = 1.f / fmaxf(qn1 * kn1, EPSF);
                *reinterpret_cast<__nv_bfloat162*>(&g_simb[(size_t)m * NKEY + gn]) =
                    __floats2bfloat162_rn(acc[mi][ni][0] * i0, acc[mi][ni][1] * i1);
                *reinterpret_cast<__nv_bfloat162*>(&g_simb[(size_t)(m + 8) * NKEY + gn]) =
                    __floats2bfloat162_rn(acc[mi][ni][2] * j0, acc[mi][ni][3] * j1);
            }
        }
    }
}

// ---------------- K3: candidate select + exact (double) rescore + exact top-32 ----------------
__global__ void k3_select(const float* __restrict__ keys) {
    const int b = blockIdx.x, t = threadIdx.x;
    __shared__ int   hist[2048];
    __shared__ float q_s[512];
    __shared__ int   cand_idx[1024];
    __shared__ float cand_sim[1024];
    __shared__ int   s_T, s_cnt;

    for (int i = t; i < 2048; i += 256) hist[i] = 0;
    q_s[t] = g_qrelu[b * 512 + t];
    q_s[t + 256] = g_qrelu[b * 512 + 256 + t];
    if (t == 0) s_cnt = 0;
    __syncthreads();

    const __nv_bfloat16* srow = &g_simb[(size_t)b * NKEY];
    for (int i = t; i < NKEY; i += 256) {
        float s = __bfloat162float(srow[i]);
        int bin = min(2047, max(0, (int)((s + 1.0f) * 1024.0f)));
        atomicAdd(&hist[bin], 1);
    }
    __syncthreads();
    if (t == 0) {
        int cum = 0, T = 0;
        for (int bi = 2047; bi >= 0; bi--) {
            cum += hist[bi];
            if (cum >= 64) { T = bi; break; }
        }
        s_T = T;
    }
    __syncthreads();
    const int T = s_T;
    for (int i = t; i < NKEY; i += 256) {
        float s = __bfloat162float(srow[i]);
        int bin = min(2047, max(0, (int)((s + 1.0f) * 1024.0f)));
        if (bin >= T) {
            int p = atomicAdd(&s_cnt, 1);
            if (p < 1024) cand_idx[p] = i;
        }
    }
    __syncthreads();
    const int cnt = min(s_cnt, 1024);

    // exact rescore in double: one warp per candidate
    const int lane = t & 31, warp = t >> 5;
    const double qn = (double)g_qn[b];
    for (int c = warp; c < cnt; c += 8) {
        const float* kp = keys + (size_t)cand_idx[c] * 512;
        double dot = 0.0, ksq = 0.0;
        for (int j = lane; j < 512; j += 32) {
            double kv = (double)kp[j];
            dot += (double)q_s[j] * kv;
            ksq += kv * kv;
        }
        for (int o = 16; o; o >>= 1) {
            dot += __shfl_xor_sync(0xffffffffu, dot, o);
            ksq += __shfl_xor_sync(0xffffffffu, ksq, o);
        }
        if (lane == 0) {
            double den = fmax(qn * sqrt(ksq), (double)EPSF);
            cand_sim[c] = (float)(dot / den);
        }
    }
    __syncthreads();

    // exact top-32 (warp 0): iterative argmax, tie -> lowest key index
    if (warp == 0) {
        for (int r = 0; r < 32; r++) {
            float best = -1e30f; int bkey = 0x7fffffff, bslot = -1;
            for (int c = lane; c < cnt; c += 32) {
                float v = cand_sim[c]; int ki = cand_idx[c];
                if (v > best || (v == best && ki < bkey)) { best = v; bkey = ki; bslot = c; }
            }
            for (int o = 16; o; o >>= 1) {
                float ov = __shfl_xor_sync(0xffffffffu, best, o);
                int   ok = __shfl_xor_sync(0xffffffffu, bkey, o);
                int   os = __shfl_xor_sync(0xffffffffu, bslot, o);
                if (ov > best || (ov == best && ok < bkey)) { best = ov; bkey = ok; bslot = os; }
            }
            if (lane == 0) {
                g_topk[b * 32 + r] = bkey;
                cand_sim[bslot] = -2e30f;
            }
            __syncwarp();
        }
    }
}

// ---------------- K4: fp32 tiled GEMM, optional row-gather, optional dual bias ----------------
// C[Mrows,256] = A[Mrows,512] @ W[512,256] (+b1+b2). BM=BN=64, BK=16, 256 thr, 4x4/thread.
__global__ void __launch_bounds__(256) k_gemm(const float* __restrict__ A,
                                              const float* __restrict__ W,
                                              const int* __restrict__ idx,
                                              const float* __restrict__ b1,
                                              const float* __restrict__ b2,
                                              float* __restrict__ C) {
    __shared__ float Ask[16][68];
    __shared__ float Wsh[16][68];
    const int t = threadIdx.x;
    const int tx = t & 15, ty = t >> 4;
    const int m0 = blockIdx.x * 64, n0 = blockIdx.y * 64;
    float acc[4][4];
#pragma unroll
    for (int i = 0; i < 4; i++)
#pragma unroll
        for (int j = 0; j < 4; j++) acc[i][j] = 0.f;

    const int lrow = t >> 2;              // 0..63
    const int kq = (t & 3) * 4;           // 0,4,8,12
    const int arow = m0 + lrow;
    const float* Abase = idx ? (A + (size_t)idx[arow] * 512) : (A + (size_t)arow * 512);
    const int wr = t >> 4;                // 0..15
    const int wc = (t & 15) * 4;

    for (int k0 = 0; k0 < 512; k0 += 16) {
        float4 av = *reinterpret_cast<const float4*>(Abase + k0 + kq);
        Ask[kq + 0][lrow] = av.x; Ask[kq + 1][lrow] = av.y;
        Ask[kq + 2][lrow] = av.z; Ask[kq + 3][lrow] = av.w;
        *reinterpret_cast<float4*>(&Wsh[wr][wc]) =
            *reinterpret_cast<const float4*>(W + (size_t)(k0 + wr) * 256 + n0 + wc);
        __syncthreads();
#pragma unroll
        for (int kk = 0; kk < 16; kk++) {
            float4 a4 = *reinterpret_cast<float4*>(&Ask[kk][ty * 4]);
            float4 b4 = *reinterpret_cast<float4*>(&Wsh[kk][tx * 4]);
            float av_[4] = {a4.x, a4.y, a4.z, a4.w};
            float bv_[4] = {b4.x, b4.y, b4.z, b4.w};
#pragma unroll
            for (int i = 0; i < 4; i++)
#pragma unroll
                for (int j = 0; j < 4; j++) acc[i][j] += av_[i] * bv_[j];
        }
        __syncthreads();
    }
#pragma unroll
    for (int i = 0; i < 4; i++) {
        int m = m0 + ty * 4 + i;
#pragma unroll
        for (int j = 0; j < 4; j++) {
            int n = n0 + tx * 4 + j;
            float v = acc[i][j];
            if (b1) v += b1[n];
            if (b2) v += b2[n];
            C[(size_t)m * 256 + n] = v;
        }
    }
}

// ---------------- K5: scores -> softmax -> attended -> classifier ----------------
__global__ void k5_final(const float* __restrict__ keys, const float* __restrict__ Ws,
                         const float* __restrict__ bs, const float* __restrict__ Wc,
                         const float* __restrict__ bc, float* __restrict__ out) {
    const int b = blockIdx.x, t = threadIdx.x, lane = t & 31, warp = t >> 5;
    __shared__ float hq_s[256], sc_s[32], w_s[32], merged[1024];
    __shared__ int idx_s[32];
    hq_s[t] = g_hq[b * 256 + t];
    if (t < 32) idx_s[t] = g_topk[b * 32 + t];
    merged[t] = g_qrelu[b * 512 + t];
    merged[256 + t] = g_qrelu[b * 512 + 256 + t];
    __syncthreads();

    for (int k = warp; k < 32; k += 8) {
        const float* Mrow = &g_M[(size_t)(b * 32 + k) * 256];
        float s = 0.f;
        for (int a = lane; a < 256; a += 32) s += tanhf(hq_s[a] + Mrow[a]) * Ws[a];
        for (int o = 16; o; o >>= 1) s += __shfl_xor_sync(0xffffffffu, s, o);
        if (lane == 0) sc_s[k] = s + bs[0];
    }
    __syncthreads();
    if (t < 32) {
        float v = sc_s[t];
        float m = v;
        for (int o = 16; o; o >>= 1) m = fmaxf(m, __shfl_xor_sync(0xffffffffu, m, o));
        float e = expf(v - m);
        float sm = e;
        for (int o = 16; o; o >>= 1) sm += __shfl_xor_sync(0xffffffffu, sm, o);
        w_s[t] = e / sm;
    }
    __syncthreads();
    for (int d = t; d < 512; d += 256) {
        float a = 0.f;
#pragma unroll 8
        for (int k = 0; k < 32; k++) a += w_s[k] * keys[(size_t)idx_s[k] * 512 + d];
        merged[512 + d] = a;
    }
    __syncthreads();
    for (int c = warp; c < 100; c += 8) {
        float s = 0.f;
        for (int j = lane; j < 1024; j += 32) s += merged[j] * Wc[j * 100 + c];
        for (int o = 16; o; o >>= 1) s += __shfl_xor_sync(0xffffffffu, s, o);
        if (lane == 0) out[b * 100 + c] = s + bc[c];
    }
}

// ---------------- launch ----------------
extern "C" void kernel_launch(void* const* d_in, const int* in_sizes, int n_in,
                              void* d_out, int out_size) {
    const float* qf   = (const float*)d_in[0];
    const float* keys = (const float*)d_in[1];
    const float* Wq   = (const float*)d_in[2];
    const float* bq   = (const float*)d_in[3];
    const float* Wm   = (const float*)d_in[4];
    const float* bm   = (const float*)d_in[5];
    const float* Ws   = (const float*)d_in[6];
    const float* bs   = (const float*)d_in[7];
    const float* Wc   = (const float*)d_in[8];
    const float* bc   = (const float*)d_in[9];
    float* out = (float*)d_out;

    int* topk_ptr = nullptr;
    float* M_ptr = nullptr; float* hq_ptr = nullptr;
    cudaGetSymbolAddress((void**)&topk_ptr, g_topk);
    cudaGetSymbolAddress((void**)&M_ptr, g_M);
    cudaGetSymbolAddress((void**)&hq_ptr, g_hq);
    float* qrelu_ptr = nullptr;
    cudaGetSymbolAddress((void**)&qrelu_ptr, g_qrelu);

    k1_prep<<<256, 256>>>(qf);
    k2_sim<<<NBLK, 256>>>(keys);
    k3_select<<<256, 256>>>(keys);
    k_gemm<<<dim3(128, 4), 256>>>(keys, Wm, topk_ptr, nullptr, nullptr, M_ptr);
    k_gemm<<<dim3(4, 4), 256>>>(qrelu_ptr, Wq, nullptr, bq, bm, hq_ptr);
    k5_final<<<256, 256>>>(keys, Ws, bs, Wc, bc, out);
}

// round 4
// speedup vs baseline: 1.2023x; 1.2023x over previous
#include <cuda_runtime.h>
#include <cuda_bf16.h>
#include <cstdint>

#define EPSF 1e-8f
#define NKEY 100000
#define NBLK 1563   // ceil(100000/64)

// ---------------- scratch (device globals; no allocs allowed) ----------------
__device__ __align__(16) __nv_bfloat16 g_simb[256 * NKEY];   // approx sims, bf16
__device__ __align__(16) float          g_qrelu[256 * 512];
__device__ __align__(16) __nv_bfloat16  g_qb[256 * 512];
__device__ __align__(16) float          g_qn[256];
__device__ __align__(16) int            g_topk[256 * 32];
__device__ __align__(16) float          g_hq[256 * 256];
__device__ __align__(16) float          g_M[8192 * 256];

#define CP_ASYNC16(dst, src) \
    asm volatile("cp.async.ca.shared.global [%0], [%1], 16;\n" :: "r"(dst), "l"(src))
#define CP_COMMIT() asm volatile("cp.async.commit_group;\n")
#define CP_WAIT0()  asm volatile("cp.async.wait_group 0;\n")

// ---------------- K1: relu(q), bf16 copy, row norms ----------------
__global__ void k1_prep(const float* __restrict__ qf) {
    const int b = blockIdx.x, t = threadIdx.x;
    __shared__ float red[8];
    float s = 0.f;
#pragma unroll
    for (int i = 0; i < 2; i++) {
        int d = t + i * 256;
        float v = fmaxf(qf[b * 512 + d], 0.f);
        g_qrelu[b * 512 + d] = v;
        g_qb[b * 512 + d] = __float2bfloat16(v);
        s += v * v;
    }
    for (int o = 16; o; o >>= 1) s += __shfl_xor_sync(0xffffffffu, s, o);
    if ((t & 31) == 0) red[t >> 5] = s;
    __syncthreads();
    if (t == 0) {
        float tot = 0.f;
        for (int i = 0; i < 8; i++) tot += red[i];
        g_qn[b] = sqrtf(tot);
    }
}

// ---------------- K2: approx sim GEMM (bf16 mma.sync), pipelined ----------------
// 256 thr (8 warps, 4Mx2N). Tile M=256 x N=64 keys, K chunks of 64, double-buffered.
__global__ void __launch_bounds__(256) k2_sim(const float* __restrict__ keys) {
    extern __shared__ __align__(16) char dsm[];
    __nv_bfloat16* As = (__nv_bfloat16*)dsm;          // 2 stages x 256x72
    __nv_bfloat16* Bs = As + 2 * 256 * 72;            // 2 stages x 64x72
    float* qn_s = (float*)(Bs + 2 * 64 * 72);         // 256
    float* kn_s = qn_s + 256;                         // 64

    const int t = threadIdx.x;
    const int n0 = blockIdx.x * 64;
    qn_s[t] = g_qn[t];

    float acc[4][4][4];
#pragma unroll
    for (int a = 0; a < 4; a++)
#pragma unroll
        for (int b = 0; b < 4; b++)
#pragma unroll
            for (int c = 0; c < 4; c++) acc[a][b][c] = 0.f;

    float ssq = 0.f;
    const int lane = t & 31, warp = t >> 5;
    const int wm = warp >> 1, wn = warp & 1;
    const int brow = t >> 2;                 // key row in tile, 0..63
    const int gn_row = n0 + brow;
    const bool rowok = gn_row < NKEY;
    const float* kptr = keys + (size_t)gn_row * 512 + (t & 3) * 16;

    const uint32_t as_base = (uint32_t)__cvta_generic_to_shared(As);
    const int am = t >> 3, akc = t & 7;      // this thread's 8 A copies: rows am+32*i

    // --- issue A chunk0 into stage 0 ---
#pragma unroll
    for (int i = 0; i < 8; i++) {
        int m = am + i * 32;
        CP_ASYNC16(as_base + (uint32_t)((m * 72 + akc * 8) * 2),
                   (const void*)&g_qb[m * 512 + 0 + akc * 8]);
    }
    CP_COMMIT();
    // --- load + convert B chunk0 into stage 0 ---
    {
        __nv_bfloat162* bs2 = reinterpret_cast<__nv_bfloat162*>(&Bs[brow * 72 + (t & 3) * 16]);
        if (rowok) {
#pragma unroll
            for (int j = 0; j < 4; j++) {
                float4 f = *reinterpret_cast<const float4*>(kptr + j * 4);
                ssq += f.x * f.x + f.y * f.y + f.z * f.z + f.w * f.w;
                bs2[2 * j]     = __floats2bfloat162_rn(f.x, f.y);
                bs2[2 * j + 1] = __floats2bfloat162_rn(f.z, f.w);
            }
        } else {
#pragma unroll
            for (int j = 0; j < 8; j++) bs2[j] = __floats2bfloat162_rn(0.f, 0.f);
        }
    }
    CP_WAIT0();
    __syncthreads();

    for (int kt = 0; kt < 8; kt++) {
        const int cur = kt & 1, nxt = cur ^ 1;
        const bool hn = kt < 7;
        // issue next A chunk (cp.async, L2-resident bf16)
        if (hn) {
            const int k0n = (kt + 1) * 64;
#pragma unroll
            for (int i = 0; i < 8; i++) {
                int m = am + i * 32;
                CP_ASYNC16(as_base + (uint32_t)(((nxt * 256 + m) * 72 + akc * 8) * 2),
                           (const void*)&g_qb[m * 512 + k0n + akc * 8]);
            }
            CP_COMMIT();
        }
        // prefetch next B chunk into registers (LDG issued before mma loop)
        float4 nf[4];
        if (hn && rowok) {
            const int k0n = (kt + 1) * 64;
#pragma unroll
            for (int j = 0; j < 4; j++)
                nf[j] = *reinterpret_cast<const float4*>(kptr + k0n + j * 4);
        }

        // ---- mma on stage cur ----
        const __nv_bfloat16* Ac = As + cur * 256 * 72;
        const __nv_bfloat16* Bc = Bs + cur * 64 * 72;
#pragma unroll
        for (int kk16 = 0; kk16 < 4; kk16++) {
            const int kk = kk16 * 16;
            uint32_t af[4][4];
#pragma unroll
            for (int mi = 0; mi < 4; mi++) {
                int row = wm * 64 + mi * 16 + (lane & 15);
                int col = kk + ((lane >> 4) << 3);
                uint32_t addr = (uint32_t)__cvta_generic_to_shared(&Ac[row * 72 + col]);
                asm volatile("ldmatrix.sync.aligned.m8n8.x4.shared.b16 {%0,%1,%2,%3}, [%4];"
                             : "=r"(af[mi][0]), "=r"(af[mi][1]), "=r"(af[mi][2]), "=r"(af[mi][3])
                             : "r"(addr));
            }
            uint32_t bfr[4][2];
#pragma unroll
            for (int p = 0; p < 2; p++) {
                int g = lane >> 3, r = lane & 7;
                int nrow = wn * 32 + p * 16 + ((g >> 1) << 3) + r;
                int kcol = kk + ((g & 1) << 3);
                uint32_t addr = (uint32_t)__cvta_generic_to_shared(&Bc[nrow * 72 + kcol]);
                uint32_t r0, r1, r2, r3;
                asm volatile("ldmatrix.sync.aligned.m8n8.x4.shared.b16 {%0,%1,%2,%3}, [%4];"
                             : "=r"(r0), "=r"(r1), "=r"(r2), "=r"(r3) : "r"(addr));
                bfr[p * 2][0] = r0;     bfr[p * 2][1] = r1;
                bfr[p * 2 + 1][0] = r2; bfr[p * 2 + 1][1] = r3;
            }
#pragma unroll
            for (int mi = 0; mi < 4; mi++)
#pragma unroll
                for (int ni = 0; ni < 4; ni++)
                    asm volatile(
                        "mma.sync.aligned.m16n8k16.row.col.f32.bf16.bf16.f32 "
                        "{%0,%1,%2,%3}, {%4,%5,%6,%7}, {%8,%9}, {%0,%1,%2,%3};"
                        : "+f"(acc[mi][ni][0]), "+f"(acc[mi][ni][1]),
                          "+f"(acc[mi][ni][2]), "+f"(acc[mi][ni][3])
                        : "r"(af[mi][0]), "r"(af[mi][1]), "r"(af[mi][2]), "r"(af[mi][3]),
                          "r"(bfr[ni][0]), "r"(bfr[ni][1]));
        }

        // convert + store next B chunk, wait next A, flip
        if (hn) {
            __nv_bfloat162* bs2 =
                reinterpret_cast<__nv_bfloat162*>(&Bs[(nxt * 64 + brow) * 72 + (t & 3) * 16]);
            if (rowok) {
#pragma unroll
                for (int j = 0; j < 4; j++) {
                    float4 f = nf[j];
                    ssq += f.x * f.x + f.y * f.y + f.z * f.z + f.w * f.w;
                    bs2[2 * j]     = __floats2bfloat162_rn(f.x, f.y);
                    bs2[2 * j + 1] = __floats2bfloat162_rn(f.z, f.w);
                }
            } else {
#pragma unroll
                for (int j = 0; j < 8; j++) bs2[j] = __floats2bfloat162_rn(0.f, 0.f);
            }
            CP_WAIT0();
        }
        __syncthreads();
    }

    // kn reduce across the 4 threads of each key row
    ssq += __shfl_xor_sync(0xffffffffu, ssq, 1);
    ssq += __shfl_xor_sync(0xffffffffu, ssq, 2);
    if ((t & 3) == 0) kn_s[brow] = sqrtf(ssq);
    __syncthreads();

    // epilogue: cosine scaling, store bf16 sims
#pragma unroll
    for (int mi = 0; mi < 4; mi++) {
        int m = wm * 64 + mi * 16 + (lane >> 2);
        float qn0 = qn_s[m], qn1 = qn_s[m + 8];
#pragma unroll
        for (int ni = 0; ni < 4; ni++) {
            int nl = wn * 32 + ni * 8 + ((lane & 3) << 1);
            int gn = n0 + nl;
            if (gn < NKEY) {
                float kn0 = kn_s[nl], kn1 = kn_s[nl + 1];
                float i0 = 1.f / fmaxf(qn0 * kn0, EPSF);
                float i1 = 1.f / fmaxf(qn0 * kn1, EPSF);
                float j0 = 1.f / fmaxf(qn1 * kn0, EPSF);
                float j1 = 1.f / fmaxf(qn1 * kn1, EPSF);
                *reinterpret_cast<__nv_bfloat162*>(&g_simb[(size_t)m * NKEY + gn]) =
                    __floats2bfloat162_rn(acc[mi][ni][0] * i0, acc[mi][ni][1] * i1);
                *reinterpret_cast<__nv_bfloat162*>(&g_simb[(size_t)(m + 8) * NKEY + gn]) =
                    __floats2bfloat162_rn(acc[mi][ni][2] * j0, acc[mi][ni][3] * j1);
            }
        }
    }
}

// ---------------- K3: candidate select + exact (double) rescore + exact top-32 ----------------
__global__ void k3_select(const float* __restrict__ keys) {
    const int b = blockIdx.x, t = threadIdx.x;
    __shared__ int   hist[2048];
    __shared__ float q_s[512];
    __shared__ int   cand_idx[1024];
    __shared__ float cand_sim[1024];
    __shared__ int   s_T, s_cnt;

    for (int i = t; i < 2048; i += 256) hist[i] = 0;
    q_s[t] = g_qrelu[b * 512 + t];
    q_s[t + 256] = g_qrelu[b * 512 + 256 + t];
    if (t == 0) s_cnt = 0;
    __syncthreads();

    const __nv_bfloat16* srow = &g_simb[(size_t)b * NKEY];
    for (int i = t; i < NKEY; i += 256) {
        float s = __bfloat162float(srow[i]);
        int bin = min(2047, max(0, (int)((s + 1.0f) * 1024.0f)));
        atomicAdd(&hist[bin], 1);
    }
    __syncthreads();
    if (t == 0) {
        int cum = 0, T = 0;
        for (int bi = 2047; bi >= 0; bi--) {
            cum += hist[bi];
            if (cum >= 64) { T = bi; break; }
        }
        s_T = T;
    }
    __syncthreads();
    const int T = s_T;
    for (int i = t; i < NKEY; i += 256) {
        float s = __bfloat162float(srow[i]);
        int bin = min(2047, max(0, (int)((s + 1.0f) * 1024.0f)));
        if (bin >= T) {
            int p = atomicAdd(&s_cnt, 1);
            if (p < 1024) cand_idx[p] = i;
        }
    }
    __syncthreads();
    const int cnt = min(s_cnt, 1024);

    // exact rescore in double: one warp per candidate
    const int lane = t & 31, warp = t >> 5;
    const double qn = (double)g_qn[b];
    for (int c = warp; c < cnt; c += 8) {
        const float* kp = keys + (size_t)cand_idx[c] * 512;
        double dot = 0.0, ksq = 0.0;
        for (int j = lane; j < 512; j += 32) {
            double kv = (double)kp[j];
            dot += (double)q_s[j] * kv;
            ksq += kv * kv;
        }
        for (int o = 16; o; o >>= 1) {
            dot += __shfl_xor_sync(0xffffffffu, dot, o);
            ksq += __shfl_xor_sync(0xffffffffu, ksq, o);
        }
        if (lane == 0) {
            double den = fmax(qn * sqrt(ksq), (double)EPSF);
            cand_sim[c] = (float)(dot / den);
        }
    }
    __syncthreads();

    // exact top-32 (warp 0): iterative argmax, tie -> lowest key index
    if (warp == 0) {
        for (int r = 0; r < 32; r++) {
            float best = -1e30f; int bkey = 0x7fffffff, bslot = -1;
            for (int c = lane; c < cnt; c += 32) {
                float v = cand_sim[c]; int ki = cand_idx[c];
                if (v > best || (v == best && ki < bkey)) { best = v; bkey = ki; bslot = c; }
            }
            for (int o = 16; o; o >>= 1) {
                float ov = __shfl_xor_sync(0xffffffffu, best, o);
                int   ok = __shfl_xor_sync(0xffffffffu, bkey, o);
                int   os = __shfl_xor_sync(0xffffffffu, bslot, o);
                if (ov > best || (ov == best && ok < bkey)) { best = ov; bkey = ok; bslot = os; }
            }
            if (lane == 0) {
                g_topk[b * 32 + r] = bkey;
                cand_sim[bslot] = -2e30f;
            }
            __syncwarp();
        }
    }
}

// ---------------- K4: tf32 tensor-core GEMM, optional row-gather, optional dual bias --------
// C[Mrows,256] = A[Mrows,512] @ W[512,256] (+b1+b2). BM=128, BN=64, BK=32.
// 256 thr = 8 warps (4M x 2N), warp tile 32x32, mma m16n8k8.
__global__ void __launch_bounds__(256) k_tf32(const float* __restrict__ A,
                                              const float* __restrict__ W,
                                              const int* __restrict__ idx,
                                              const float* __restrict__ b1,
                                              const float* __restrict__ b2,
                                              float* __restrict__ C) {
    __shared__ uint32_t AsU[128 * 36];
    __shared__ uint32_t BsU[32 * 72];
    const int t = threadIdx.x;
    const int lane = t & 31, warp = t >> 5;
    const int wm = (warp >> 1) * 32, wn = (warp & 1) * 32;
    const int m0 = blockIdx.x * 128, n0 = blockIdx.y * 64;

    float acc[2][4][4];
#pragma unroll
    for (int i = 0; i < 2; i++)
#pragma unroll
        for (int j = 0; j < 4; j++)
#pragma unroll
            for (int k = 0; k < 4; k++) acc[i][j][k] = 0.f;

    const int alrow = t >> 1;                   // 0..127
    const int acol0 = (t & 1) * 16;             // 0 or 16
    const float* arow = (idx ? (A + (size_t)idx[m0 + alrow] * 512)
                             : (A + (size_t)(m0 + alrow) * 512)) + acol0;
    const int wr = t >> 3;                      // 0..31
    const int wc = (t & 7) * 8;
    const float* wrow = W + (size_t)wr * 256 + n0 + wc;

    for (int k0 = 0; k0 < 512; k0 += 32) {
        // A tile: 128x32 fp32 -> tf32 bits
#pragma unroll
        for (int q = 0; q < 4; q++) {
            float4 f = *reinterpret_cast<const float4*>(arow + k0 + q * 4);
            uint4 u;
            asm("cvt.rna.tf32.f32 %0, %1;" : "=r"(u.x) : "f"(f.x));
            asm("cvt.rna.tf32.f32 %0, %1;" : "=r"(u.y) : "f"(f.y));
            asm("cvt.rna.tf32.f32 %0, %1;" : "=r"(u.z) : "f"(f.z));
            asm("cvt.rna.tf32.f32 %0, %1;" : "=r"(u.w) : "f"(f.w));
            *reinterpret_cast<uint4*>(&AsU[alrow * 36 + acol0 + q * 4]) = u;
        }
        // W tile: 32x64
#pragma unroll
        for (int q = 0; q < 2; q++) {
            float4 f = *reinterpret_cast<const float4*>(wrow + (size_t)k0 * 256 + q * 4);
            uint4 u;
            asm("cvt.rna.tf32.f32 %0, %1;" : "=r"(u.x) : "f"(f.x));
            asm("cvt.rna.tf32.f32 %0, %1;" : "=r"(u.y) : "f"(f.y));
            asm("cvt.rna.tf32.f32 %0, %1;" : "=r"(u.z) : "f"(f.z));
            asm("cvt.rna.tf32.f32 %0, %1;" : "=r"(u.w) : "f"(f.w));
            *reinterpret_cast<uint4*>(&BsU[wr * 72 + wc + q * 4]) = u;
        }
        __syncthreads();
#pragma unroll
        for (int ks = 0; ks < 4; ks++) {
            const int kc = ks * 8;
            uint32_t a[2][4];
#pragma unroll
            for (int mi = 0; mi < 2; mi++) {
                int r0 = wm + mi * 16 + (lane >> 2);
                a[mi][0] = AsU[r0 * 36 + kc + (lane & 3)];
                a[mi][1] = AsU[(r0 + 8) * 36 + kc + (lane & 3)];
                a[mi][2] = AsU[r0 * 36 + kc + (lane & 3) + 4];
                a[mi][3] = AsU[(r0 + 8) * 36 + kc + (lane & 3) + 4];
            }
            uint32_t bb[4][2];
#pragma unroll
            for (int ni = 0; ni < 4; ni++) {
                int nc = wn + ni * 8 + (lane >> 2);
                bb[ni][0] = BsU[(kc + (lane & 3)) * 72 + nc];
                bb[ni][1] = BsU[(kc + (lane & 3) + 4) * 72 + nc];
            }
#pragma unroll
            for (int mi = 0; mi < 2; mi++)
#pragma unroll
                for (int ni = 0; ni < 4; ni++)
                    asm volatile(
                        "mma.sync.aligned.m16n8k8.row.col.f32.tf32.tf32.f32 "
                        "{%0,%1,%2,%3}, {%4,%5,%6,%7}, {%8,%9}, {%0,%1,%2,%3};"
                        : "+f"(acc[mi][ni][0]), "+f"(acc[mi][ni][1]),
                          "+f"(acc[mi][ni][2]), "+f"(acc[mi][ni][3])
                        : "r"(a[mi][0]), "r"(a[mi][1]), "r"(a[mi][2]), "r"(a[mi][3]),
                          "r"(bb[ni][0]), "r"(bb[ni][1]));
        }
        __syncthreads();
    }

#pragma unroll
    for (int mi = 0; mi < 2; mi++) {
        int r0 = m0 + wm + mi * 16 + (lane >> 2);
#pragma unroll
        for (int ni = 0; ni < 4; ni++) {
            int c0 = n0 + wn + ni * 8 + (lane & 3) * 2;
            float add0 = (b1 ? b1[c0] : 0.f) + (b2 ? b2[c0] : 0.f);
            float add1 = (b1 ? b1[c0 + 1] : 0.f) + (b2 ? b2[c0 + 1] : 0.f);
            C[(size_t)r0 * 256 + c0]           = acc[mi][ni][0] + add0;
            C[(size_t)r0 * 256 + c0 + 1]       = acc[mi][ni][1] + add1;
            C[(size_t)(r0 + 8) * 256 + c0]     = acc[mi][ni][2] + add0;
            C[(size_t)(r0 + 8) * 256 + c0 + 1] = acc[mi][ni][3] + add1;
        }
    }
}

// ---------------- K5: scores -> softmax -> attended -> classifier ----------------
__global__ void k5_final(const float* __restrict__ keys, const float* __restrict__ Ws,
                         const float* __restrict__ bs, const float* __restrict__ Wc,
                         const float* __restrict__ bc, float* __restrict__ out) {
    const int b = blockIdx.x, t = threadIdx.x, lane = t & 31, warp = t >> 5;
    __shared__ float hq_s[256], sc_s[32], w_s[32], merged[1024];
    __shared__ int idx_s[32];
    hq_s[t] = g_hq[b * 256 + t];
    if (t < 32) idx_s[t] = g_topk[b * 32 + t];
    merged[t] = g_qrelu[b * 512 + t];
    merged[256 + t] = g_qrelu[b * 512 + 256 + t];
    __syncthreads();

    for (int k = warp; k < 32; k += 8) {
        const float* Mrow = &g_M[(size_t)(b * 32 + k) * 256];
        float s = 0.f;
        for (int a = lane; a < 256; a += 32) s += tanhf(hq_s[a] + Mrow[a]) * Ws[a];
        for (int o = 16; o; o >>= 1) s += __shfl_xor_sync(0xffffffffu, s, o);
        if (lane == 0) sc_s[k] = s + bs[0];
    }
    __syncthreads();
    if (t < 32) {
        float v = sc_s[t];
        float m = v;
        for (int o = 16; o; o >>= 1) m = fmaxf(m, __shfl_xor_sync(0xffffffffu, m, o));
        float e = expf(v - m);
        float sm = e;
        for (int o = 16; o; o >>= 1) sm += __shfl_xor_sync(0xffffffffu, sm, o);
        w_s[t] = e / sm;
    }
    __syncthreads();
    for (int d = t; d < 512; d += 256) {
        float a = 0.f;
#pragma unroll 8
        for (int k = 0; k < 32; k++) a += w_s[k] * keys[(size_t)idx_s[k] * 512 + d];
        merged[512 + d] = a;
    }
    __syncthreads();
    for (int c = warp; c < 100; c += 8) {
        float s = 0.f;
        for (int j = lane; j < 1024; j += 32) s += merged[j] * Wc[j * 100 + c];
        for (int o = 16; o; o >>= 1) s += __shfl_xor_sync(0xffffffffu, s, o);
        if (lane == 0) out[b * 100 + c] = s + bc[c];
    }
}

// ---------------- launch ----------------
extern "C" void kernel_launch(void* const* d_in, const int* in_sizes, int n_in,
                              void* d_out, int out_size) {
    const float* qf   = (const float*)d_in[0];
    const float* keys = (const float*)d_in[1];
    const float* Wq   = (const float*)d_in[2];
    const float* bq   = (const float*)d_in[3];
    const float* Wm   = (const float*)d_in[4];
    const float* bm   = (const float*)d_in[5];
    const float* Ws   = (const float*)d_in[6];
    const float* bs   = (const float*)d_in[7];
    const float* Wc   = (const float*)d_in[8];
    const float* bc   = (const float*)d_in[9];
    float* out = (float*)d_out;

    int* topk_ptr = nullptr;
    float* M_ptr = nullptr; float* hq_ptr = nullptr; float* qrelu_ptr = nullptr;
    cudaGetSymbolAddress((void**)&topk_ptr, g_topk);
    cudaGetSymbolAddress((void**)&M_ptr, g_M);
    cudaGetSymbolAddress((void**)&hq_ptr, g_hq);
    cudaGetSymbolAddress((void**)&qrelu_ptr, g_qrelu);

    const int k2_smem = (2 * 256 * 72 + 2 * 64 * 72) * 2 + (256 + 64) * 4;
    cudaFuncSetAttribute(k2_sim, cudaFuncAttributeMaxDynamicSharedMemorySize, k2_smem);

    k1_prep<<<256, 256>>>(qf);
    k2_sim<<<NBLK, 256, k2_smem>>>(keys);
    k3_select<<<256, 256>>>(keys);
    k_tf32<<<dim3(64, 4), 256>>>(keys, Wm, topk_ptr, nullptr, nullptr, M_ptr);
    k_tf32<<<dim3(2, 4), 256>>>(qrelu_ptr, Wq, nullptr, bq, bm, hq_ptr);
    k5_final<<<256, 256>>>(keys, Ws, bs, Wc, bc, out);
}